// round 11
// baseline (speedup 1.0000x reference)
#include <cuda_runtime.h>

#define Lseq 65536
#define D 512
#define H 4
#define HD 128
// scale * log2(e): scores computed in log2 domain, w = ex2(score)
#define SCALE2 (0.08838834764831845f * 1.4426950408889634f)

#define NB 148           // K3 blocks (1 per SM)
#define K3_THREADS 384
#define K3_WARPS 12
#define RING_BYTES (K3_WARPS*3*4096)   // 147456

typedef unsigned long long ull;

// ---------------- scratch (device globals; no allocation allowed) ----------
__device__ float g_q[D];
__device__ float g_ug[H*D];
__device__ float g_pse[H*NB];
__device__ float g_pam[H*NB];
__device__ float g_pzx[NB*H*D];
__device__ float g_z[H*D];
__device__ float g_opre[D];
__device__ float g_y[D];
__device__ float g_h1[D];

// ---------------- f32x2 packed helpers ------------------------------------
__device__ __forceinline__ ull pk2(float lo, float hi) {
    ull r; asm("mov.b64 %0,{%1,%2};" : "=l"(r) : "f"(lo), "f"(hi)); return r;
}
__device__ __forceinline__ void upk2(ull v, float& lo, float& hi) {
    asm("mov.b64 {%0,%1},%2;" : "=f"(lo), "=f"(hi) : "l"(v));
}
__device__ __forceinline__ ull fma2(ull a, ull b, ull c) {
    ull r; asm("fma.rn.f32x2 %0,%1,%2,%3;" : "=l"(r) : "l"(a), "l"(b), "l"(c)); return r;
}
__device__ __forceinline__ ull add2(ull a, ull b) {
    ull r; asm("add.rn.f32x2 %0,%1,%2;" : "=l"(r) : "l"(a), "l"(b)); return r;
}
__device__ __forceinline__ ull mul2(ull a, ull b) {
    ull r; asm("mul.rn.f32x2 %0,%1,%2;" : "=l"(r) : "l"(a), "l"(b)); return r;
}
__device__ __forceinline__ float ex2f(float x) {
    float y; asm("ex2.approx.f32 %0, %1;" : "=f"(y) : "f"(x)); return y;
}
// warp all-reduce via butterfly (redux.f32 does NOT exist on sm_103)
__device__ __forceinline__ float redux_add(float v) {
    #pragma unroll
    for (int o = 16; o; o >>= 1) v += __shfl_xor_sync(~0u, v, o);
    return v;
}

// ---------------- cp.async helpers ----------------------------------------
#define CPA(sa, ga) asm volatile("cp.async.cg.shared.global [%0], [%1], 16;" :: "r"(sa), "l"(ga))
#define CPC()       asm volatile("cp.async.commit_group;")
#define CPW(n)      asm volatile("cp.async.wait_group %0;" :: "n"(n))

// ---- warp GEMV: dot(w_row[0:512], v[0:512]) via float4 + butterfly --------
__device__ __forceinline__ float dot512(const float4* __restrict__ w4,
                                        const float4* __restrict__ v4, int lane) {
    float acc = 0.f;
    #pragma unroll
    for (int j = 0; j < 4; j++) {
        float4 w = w4[lane + 32*j];
        float4 s = v4[lane + 32*j];
        acc = fmaf(w.x, s.x, acc); acc = fmaf(w.y, s.y, acc);
        acc = fmaf(w.z, s.z, acc); acc = fmaf(w.w, s.w, acc);
    }
    return redux_add(acc);
}

// =================== K1: xn0 = LN(x[0]); q = Wq xn0 + bq ===================
__global__ void k1_q(const float* __restrict__ x, const float* __restrict__ w_in,
                     const float* __restrict__ b_in, const float* __restrict__ g1,
                     const float* __restrict__ be1) {
    int lane = threadIdx.x & 31;
    int r = blockIdx.x*8 + (threadIdx.x >> 5);
    const float4* x4 = reinterpret_cast<const float4*>(x);
    float4 xl[4]; float s1 = 0.f, s2 = 0.f;
    #pragma unroll
    for (int j = 0; j < 4; j++) {
        xl[j] = x4[lane + 32*j];
        s1 += xl[j].x + xl[j].y + xl[j].z + xl[j].w;
        s2 = fmaf(xl[j].x, xl[j].x, s2); s2 = fmaf(xl[j].y, xl[j].y, s2);
        s2 = fmaf(xl[j].z, xl[j].z, s2); s2 = fmaf(xl[j].w, xl[j].w, s2);
    }
    s1 = redux_add(s1); s2 = redux_add(s2);
    float mean = s1 * (1.f/D);
    float rstd = rsqrtf(s2 * (1.f/D) - mean*mean + 1e-5f);

    const float4* g14  = reinterpret_cast<const float4*>(g1);
    const float4* be14 = reinterpret_cast<const float4*>(be1);
    const float4* w4   = reinterpret_cast<const float4*>(w_in + (size_t)r * D);
    float acc = 0.f;
    #pragma unroll
    for (int j = 0; j < 4; j++) {
        float4 g = g14[lane + 32*j], b = be14[lane + 32*j], w = w4[lane + 32*j];
        float nx = (xl[j].x - mean)*rstd*g.x + b.x;
        float ny = (xl[j].y - mean)*rstd*g.y + b.y;
        float nz = (xl[j].z - mean)*rstd*g.z + b.z;
        float nw = (xl[j].w - mean)*rstd*g.w + b.w;
        acc = fmaf(w.x, nx, acc); acc = fmaf(w.y, ny, acc);
        acc = fmaf(w.z, nz, acc); acc = fmaf(w.w, nw, acc);
    }
    acc = redux_add(acc);
    if (lane == 0) g_q[r] = acc + b_in[r];
}

// ====== K2: ug[h*D+d] = SCALE2*g1[d]* (Wk_h^T q_h)[d]  (log2e folded) ======
__global__ void k2_u(const float* __restrict__ w_in, const float* __restrict__ g1) {
    __shared__ float red[8][32];
    __shared__ float qs[HD];
    int tid = threadIdx.x;
    int h  = blockIdx.x >> 4;
    int dc = blockIdx.x & 15;
    if (tid < HD) qs[tid] = g_q[h*HD + tid];
    __syncthreads();
    int c  = tid & 31;
    int ic = tid >> 5;
    int col = dc*32 + c;
    const float* wb = w_in + (size_t)(D + h*HD + ic*16) * D + col;
    float a0 = 0.f, a1 = 0.f, a2 = 0.f, a3 = 0.f;
    #pragma unroll
    for (int i = 0; i < 16; i += 4) {
        a0 = fmaf(wb[(size_t)(i+0) * D], qs[ic*16 + i+0], a0);
        a1 = fmaf(wb[(size_t)(i+1) * D], qs[ic*16 + i+1], a1);
        a2 = fmaf(wb[(size_t)(i+2) * D], qs[ic*16 + i+2], a2);
        a3 = fmaf(wb[(size_t)(i+3) * D], qs[ic*16 + i+3], a3);
    }
    red[ic][c] = (a0 + a1) + (a2 + a3);
    __syncthreads();
    if (tid < 32) {
        float s = 0.f;
        #pragma unroll
        for (int k = 0; k < 8; k++) s += red[k][tid];
        int d = dc*32 + tid;
        g_ug[h*D + d] = SCALE2 * g1[d] * s;
    }
}

// =================== K3: fused LN + scores + softmax + ZX ==================
// 12 warps/block (3/SMSP). Warp owns 37 rows (gw<1600) else 36 = 19/18 pairs.
// Software-pipelined; half-split butterfly reduction; centered u in registers;
// staged non-atomic zx tail.
__global__ void __launch_bounds__(K3_THREADS, 1)
k3_main(const float* __restrict__ x) {
    extern __shared__ __align__(16) float ring[];   // 12 warps * 3 slots * 1024 f
    __shared__ float sm_se[K3_WARPS][H], sm_am[K3_WARPS][H];

    int tid = threadIdx.x, lane = tid & 31, warp = tid >> 5;

    // ---- u into registers, center: u' = u - sug/D ----
    const float4* ug4 = reinterpret_cast<const float4*>(g_ug);
    ull u0[8], u1[8], u2[8], u3[8];
    {
        #pragma unroll
        for (int h = 0; h < 4; h++) {
            float acc = 0.f;
            #pragma unroll
            for (int j = 0; j < 4; j++) {
                float4 u = ug4[h*128 + lane + 32*j];
                ull plo = pk2(u.x, u.y), phi = pk2(u.z, u.w);
                if (h == 0) { u0[2*j] = plo; u0[2*j+1] = phi; }
                if (h == 1) { u1[2*j] = plo; u1[2*j+1] = phi; }
                if (h == 2) { u2[2*j] = plo; u2[2*j+1] = phi; }
                if (h == 3) { u3[2*j] = plo; u3[2*j+1] = phi; }
                acc += (u.x + u.y) + (u.z + u.w);
            }
            acc = redux_add(acc);
            float nm = -acc * (1.f/D);
            ull nm2 = pk2(nm, nm);
            #pragma unroll
            for (int k = 0; k < 8; k++) {
                if (h == 0) u0[k] = add2(u0[k], nm2);
                if (h == 1) u1[k] = add2(u1[k], nm2);
                if (h == 2) u2[k] = add2(u2[k], nm2);
                if (h == 3) u3[k] = add2(u3[k], nm2);
            }
        }
    }

    float se0 = 0.f, se1 = 0.f, se2 = 0.f, se3 = 0.f;
    float am0 = 0.f, am1 = 0.f, am2 = 0.f, am3 = 0.f;
    ull zx0[8], zx1[8], zx2[8], zx3[8];
    #pragma unroll
    for (int k = 0; k < 8; k++) { zx0[k]=0ull; zx1[k]=0ull; zx2[k]=0ull; zx3[k]=0ull; }

    const float4* xb = reinterpret_cast<const float4*>(x);
    int gw = blockIdx.x * K3_WARPS + warp;            // 0..1775
    int start = gw*36 + (gw < 1600 ? gw : 1600);      // 65536 = 1600*37 + 176*36
    int cnt   = 36 + (gw < 1600 ? 1 : 0);
    int npairs = (cnt + 1) >> 1;                      // 19 or 18

    unsigned warp_base = (unsigned)__cvta_generic_to_shared(ring) + warp * 3 * 4096;
    bool lowh = (lane & 16) == 0;

    auto refill = [&](int q, int slotn) {
        #pragma unroll
        for (int rr = 0; rr < 2; rr++) {
            int l = start + 2*q + rr;
            if (l > start + cnt - 1) l = start;     // masked row: safe addr
            unsigned sa = warp_base + slotn*4096 + rr*2048 + lane*16;
            const float4* g = xb + (size_t)l * 128 + lane;
            CPA(sa,       g);
            CPA(sa+32*16, g+32);
            CPA(sa+64*16, g+64);
            CPA(sa+96*16, g+96);
        }
    };
    auto ldpair = [&](int slotn, ull* A, ull* B) {
        const ulonglong2* s8 = reinterpret_cast<const ulonglong2*>(ring + warp*3072 + slotn*1024);
        ulonglong2 t;
        t = s8[lane];      A[0]=t.x; A[1]=t.y;
        t = s8[lane+32];   A[2]=t.x; A[3]=t.y;
        t = s8[lane+64];   A[4]=t.x; A[5]=t.y;
        t = s8[lane+96];   A[6]=t.x; A[7]=t.y;
        t = s8[lane+128];  B[0]=t.x; B[1]=t.y;
        t = s8[lane+160];  B[2]=t.x; B[3]=t.y;
        t = s8[lane+192];  B[4]=t.x; B[5]=t.y;
        t = s8[lane+224];  B[6]=t.x; B[7]=t.y;
    };
    // P layout: [s1a,s2a,e0a,e1a,e2a,e3a, s1b,s2b,e0b,e1b,e2b,e3b]
    auto partials = [&](const ull* A, const ull* B, float* P) {
        ull spA = A[0], qpA = mul2(A[0], A[0]);
        ull spB = B[0], qpB = mul2(B[0], B[0]);
        #pragma unroll
        for (int i = 1; i < 8; i++) {
            spA = add2(spA, A[i]); qpA = fma2(A[i], A[i], qpA);
            spB = add2(spB, B[i]); qpB = fma2(B[i], B[i], qpB);
        }
        ull d0A=0, d1A=0, d2A=0, d3A=0, d0B=0, d1B=0, d2B=0, d3B=0;
        #pragma unroll
        for (int k = 0; k < 8; k++) {
            d0A = fma2(A[k], u0[k], d0A); d0B = fma2(B[k], u0[k], d0B);
            d1A = fma2(A[k], u1[k], d1A); d1B = fma2(B[k], u1[k], d1B);
            d2A = fma2(A[k], u2[k], d2A); d2B = fma2(B[k], u2[k], d2B);
            d3A = fma2(A[k], u3[k], d3A); d3B = fma2(B[k], u3[k], d3B);
        }
        float t0, t1;
        upk2(spA,t0,t1); P[0] = t0+t1;  upk2(qpA,t0,t1); P[1] = t0+t1;
        upk2(d0A,t0,t1); P[2] = t0+t1;  upk2(d1A,t0,t1); P[3] = t0+t1;
        upk2(d2A,t0,t1); P[4] = t0+t1;  upk2(d3A,t0,t1); P[5] = t0+t1;
        upk2(spB,t0,t1); P[6] = t0+t1;  upk2(qpB,t0,t1); P[7] = t0+t1;
        upk2(d0B,t0,t1); P[8] = t0+t1;  upk2(d1B,t0,t1); P[9] = t0+t1;
        upk2(d2B,t0,t1); P[10]= t0+t1;  upk2(d3B,t0,t1); P[11]= t0+t1;
    };
    // half-split 12-value all-reduce: 42 SHFL + 36 FADD (vs 60/60 naive)
    auto reduce12 = [&](float* P) {
        #pragma unroll
        for (int k = 0; k < 12; k++) P[k] += __shfl_xor_sync(~0u, P[k], 16);
        float q[6];
        #pragma unroll
        for (int j = 0; j < 6; j++) q[j] = lowh ? P[2*j] : P[2*j+1];
        #pragma unroll
        for (int o = 8; o; o >>= 1) {
            #pragma unroll
            for (int j = 0; j < 6; j++) q[j] += __shfl_xor_sync(~0u, q[j], o);
        }
        #pragma unroll
        for (int j = 0; j < 6; j++) {
            float r = __shfl_xor_sync(~0u, q[j], 16);
            P[2*j]   = lowh ? q[j] : r;
            P[2*j+1] = lowh ? r : q[j];
        }
    };
    auto update = [&](const float* P, const ull* A, const ull* B, float validB) {
        {   // row A
            float mean = P[0] * (1.f/D);
            float rstd = rsqrtf(P[1] * (1.f/D) - mean*mean + 1e-5f);
            float w0 = ex2f(rstd * P[2]);
            float w1 = ex2f(rstd * P[3]);
            float w2 = ex2f(rstd * P[4]);
            float w3 = ex2f(rstd * P[5]);
            se0 += w0; se1 += w1; se2 += w2; se3 += w3;
            float wr0 = w0*rstd, wr1 = w1*rstd, wr2 = w2*rstd, wr3 = w3*rstd;
            am0 = fmaf(wr0, mean, am0); am1 = fmaf(wr1, mean, am1);
            am2 = fmaf(wr2, mean, am2); am3 = fmaf(wr3, mean, am3);
            ull p0 = pk2(wr0,wr0), p1 = pk2(wr1,wr1), p2 = pk2(wr2,wr2), p3 = pk2(wr3,wr3);
            #pragma unroll
            for (int k = 0; k < 8; k++) {
                zx0[k] = fma2(A[k], p0, zx0[k]);
                zx1[k] = fma2(A[k], p1, zx1[k]);
                zx2[k] = fma2(A[k], p2, zx2[k]);
                zx3[k] = fma2(A[k], p3, zx3[k]);
            }
        }
        {   // row B (masked on last pair of odd-count chunks)
            float mean = P[6] * (1.f/D);
            float rstd = rsqrtf(P[7] * (1.f/D) - mean*mean + 1e-5f);
            float w0 = validB * ex2f(rstd * P[8]);
            float w1 = validB * ex2f(rstd * P[9]);
            float w2 = validB * ex2f(rstd * P[10]);
            float w3 = validB * ex2f(rstd * P[11]);
            se0 += w0; se1 += w1; se2 += w2; se3 += w3;
            float wr0 = w0*rstd, wr1 = w1*rstd, wr2 = w2*rstd, wr3 = w3*rstd;
            am0 = fmaf(wr0, mean, am0); am1 = fmaf(wr1, mean, am1);
            am2 = fmaf(wr2, mean, am2); am3 = fmaf(wr3, mean, am3);
            ull p0 = pk2(wr0,wr0), p1 = pk2(wr1,wr1), p2 = pk2(wr2,wr2), p3 = pk2(wr3,wr3);
            #pragma unroll
            for (int k = 0; k < 8; k++) {
                zx0[k] = fma2(B[k], p0, zx0[k]);
                zx1[k] = fma2(B[k], p1, zx1[k]);
                zx2[k] = fma2(B[k], p2, zx2[k]);
                zx3[k] = fma2(B[k], p3, zx3[k]);
            }
        }
    };

    // ---- prologue: prefetch pairs 0..2 ----
    #pragma unroll
    for (int pp = 0; pp < 3; pp++) { refill(pp, pp); CPC(); }

    ull ca[8], cb[8]; float cp[12];
    CPW(2);
    ldpair(0, ca, cb);
    refill(3, 0); CPC();
    partials(ca, cb, cp);

    #pragma unroll 3
    for (int p = 0; p < npairs - 1; p++) {
        ull na[8], nb[8]; float np[12];
        CPW(2);
        ldpair((p+1)%3, na, nb);
        if (p + 4 < npairs) refill(p+4, (p+1)%3);
        CPC();
        partials(na, nb, np);          // independent FMAs fill shuffle stalls

        reduce12(cp);
        update(cp, ca, cb, 1.f);       // non-tail pairs: both rows valid

        #pragma unroll
        for (int k = 0; k < 8; k++) { ca[k] = na[k]; cb[k] = nb[k]; }
        #pragma unroll
        for (int k = 0; k < 12; k++) cp[k] = np[k];
    }
    // tail pair
    {
        reduce12(cp);
        float validB = (2*(npairs-1) + 1 < cnt) ? 1.f : 0.f;
        update(cp, ca, cb, validB);
    }

    // ---- block combine (se/am are warp-uniform) ----
    if (lane == 0) {
        sm_se[warp][0]=se0; sm_se[warp][1]=se1; sm_se[warp][2]=se2; sm_se[warp][3]=se3;
        sm_am[warp][0]=am0; sm_am[warp][1]=am1; sm_am[warp][2]=am2; sm_am[warp][3]=am3;
    }
    // ---- stage zx into (now dead) ring smem: warp w owns ring[w*2048..] ----
    CPW(0);
    __syncthreads();     // all warps done with ring slots AND sm_se/sm_am written
    if (tid < H) {
        int h = tid;
        float bse = 0.f, bam = 0.f;
        #pragma unroll
        for (int w = 0; w < K3_WARPS; w++) { bse += sm_se[w][h]; bam += sm_am[w][h]; }
        g_pse[h*NB + blockIdx.x] = bse;
        g_pam[h*NB + blockIdx.x] = bam;
    }
    {
        float z0[16], z1[16], z2[16], z3[16];
        #pragma unroll
        for (int k = 0; k < 8; k++) {
            upk2(zx0[k], z0[2*k], z0[2*k+1]);
            upk2(zx1[k], z1[2*k], z1[2*k+1]);
            upk2(zx2[k], z2[2*k], z2[2*k+1]);
            upk2(zx3[k], z3[2*k], z3[2*k+1]);
        }
        float* wb = ring + warp*2048;
        #pragma unroll
        for (int j = 0; j < 4; j++) {
            *reinterpret_cast<float4*>(wb + 0*512 + j*128 + 4*lane) =
                make_float4(z0[4*j], z0[4*j+1], z0[4*j+2], z0[4*j+3]);
            *reinterpret_cast<float4*>(wb + 1*512 + j*128 + 4*lane) =
                make_float4(z1[4*j], z1[4*j+1], z1[4*j+2], z1[4*j+3]);
            *reinterpret_cast<float4*>(wb + 2*512 + j*128 + 4*lane) =
                make_float4(z2[4*j], z2[4*j+1], z2[4*j+2], z2[4*j+3]);
            *reinterpret_cast<float4*>(wb + 3*512 + j*128 + 4*lane) =
                make_float4(z3[4*j], z3[4*j+1], z3[4*j+2], z3[4*j+3]);
        }
    }
    __syncthreads();
    // ---- tree-reduce 12 warp copies -> g_pzx (dense float4, no conflicts) --
    for (int idx = tid; idx < 512; idx += K3_THREADS) {
        float4 a = make_float4(0.f,0.f,0.f,0.f);
        #pragma unroll
        for (int w = 0; w < K3_WARPS; w++) {
            float4 v = *reinterpret_cast<const float4*>(ring + w*2048 + 4*idx);
            a.x += v.x; a.y += v.y; a.z += v.z; a.w += v.w;
        }
        reinterpret_cast<float4*>(g_pzx + (size_t)blockIdx.x*(H*D))[idx] = a;
    }
}

// ======== K4: z = g1*(sum_b ZX - AM)/SE + be1 (plain sums) =================
// grid 64 = (h:4, dchunk:16 of 32 cols), 512 threads (16 warps, high MLP)
__global__ void __launch_bounds__(512, 2)
k4_z(const float* __restrict__ g1, const float* __restrict__ be1) {
    int h = blockIdx.x >> 4;
    int dbase = (blockIdx.x & 15) * 32;
    int tid = threadIdx.x, lane = tid & 31, warp = tid >> 5;
    __shared__ float part[16][32];
    __shared__ float sSE, sAM;

    if (warp == 0) {
        float se = 0.f;
        #pragma unroll
        for (int b = lane; b < NB; b += 32) se += g_pse[h*NB + b];
        se = redux_add(se);
        if (lane == 0) sSE = se;
    } else if (warp == 1) {
        float am = 0.f;
        #pragma unroll
        for (int b = lane; b < NB; b += 32) am += g_pam[h*NB + b];
        am = redux_add(am);
        if (lane == 0) sAM = am;
    }

    float acc = 0.f;
    int b0 = warp * 10;
    int be = b0 + 10 < NB ? b0 + 10 : NB;
    #pragma unroll 5
    for (int b = b0; b < be; b++)
        acc += g_pzx[(size_t)b*(H*D) + h*D + dbase + lane];
    part[warp][lane] = acc;
    __syncthreads();
    if (warp == 0) {
        float s = part[0][lane];
        #pragma unroll
        for (int w = 1; w < 16; w++) s += part[w][lane];
        int d = dbase + lane;
        g_z[h*D + d] = g1[d] * (s - sAM) / sSE + be1[d];
    }
}

// ========= K5: o_pre[r] = dot(Wv[r], z_{head(r)}) + bv[r]  (warp per row) ==
__global__ void k5_ov(const float* __restrict__ w_in, const float* __restrict__ b_in) {
    int lane = threadIdx.x & 31;
    int r = blockIdx.x*8 + (threadIdx.x >> 5);
    const float4* w4 = reinterpret_cast<const float4*>(w_in + (size_t)(2*D + r) * D);
    const float4* v4 = reinterpret_cast<const float4*>(g_z + (r >> 7) * D);
    float acc = dot512(w4, v4, lane);
    if (lane == 0) g_opre[r] = acc + b_in[2*D + r];
}

// ========= K6: y = x[0] + w_out @ o_pre + b_out  (warp per row) ============
__global__ void k6_out(const float* __restrict__ x, const float* __restrict__ w_out,
                       const float* __restrict__ b_out) {
    int lane = threadIdx.x & 31;
    int r = blockIdx.x*8 + (threadIdx.x >> 5);
    const float4* w4 = reinterpret_cast<const float4*>(w_out + (size_t)r * D);
    const float4* v4 = reinterpret_cast<const float4*>(g_opre);
    float acc = dot512(w4, v4, lane);
    if (lane == 0) g_y[r] = x[r] + acc + b_out[r];
}

// ========= K7: h1 = relu(LN(y,g2,be2) @ w1^T + b1)  (warp per row) =========
__global__ void k7_mlp1(const float* __restrict__ w1, const float* __restrict__ b1,
                        const float* __restrict__ g2, const float* __restrict__ be2) {
    int lane = threadIdx.x & 31;
    int r = blockIdx.x*8 + (threadIdx.x >> 5);
    const float4* y4 = reinterpret_cast<const float4*>(g_y);
    float4 yl[4]; float s1 = 0.f, s2 = 0.f;
    #pragma unroll
    for (int j = 0; j < 4; j++) {
        yl[j] = y4[lane + 32*j];
        s1 += yl[j].x + yl[j].y + yl[j].z + yl[j].w;
        s2 = fmaf(yl[j].x, yl[j].x, s2); s2 = fmaf(yl[j].y, yl[j].y, s2);
        s2 = fmaf(yl[j].z, yl[j].z, s2); s2 = fmaf(yl[j].w, yl[j].w, s2);
    }
    s1 = redux_add(s1); s2 = redux_add(s2);
    float mean = s1 * (1.f/D);
    float rstd = rsqrtf(s2 * (1.f/D) - mean*mean + 1e-5f);

    const float4* g24  = reinterpret_cast<const float4*>(g2);
    const float4* be24 = reinterpret_cast<const float4*>(be2);
    const float4* w4   = reinterpret_cast<const float4*>(w1 + (size_t)r * D);
    float acc = 0.f;
    #pragma unroll
    for (int j = 0; j < 4; j++) {
        float4 g = g24[lane + 32*j], b = be24[lane + 32*j], w = w4[lane + 32*j];
        float nx = (yl[j].x - mean)*rstd*g.x + b.x;
        float ny = (yl[j].y - mean)*rstd*g.y + b.y;
        float nz = (yl[j].z - mean)*rstd*g.z + b.z;
        float nw = (yl[j].w - mean)*rstd*g.w + b.w;
        acc = fmaf(w.x, nx, acc); acc = fmaf(w.y, ny, acc);
        acc = fmaf(w.z, nz, acc); acc = fmaf(w.w, nw, acc);
    }
    acc = redux_add(acc);
    if (lane == 0) g_h1[r] = fmaxf(acc + b1[r], 0.f);
}

// ========= K8: out = y + w2 @ h1 + b2  (warp per row) ======================
__global__ void k8_mlp2(const float* __restrict__ w2, const float* __restrict__ b2,
                        float* __restrict__ out) {
    int lane = threadIdx.x & 31;
    int r = blockIdx.x*8 + (threadIdx.x >> 5);
    const float4* w4 = reinterpret_cast<const float4*>(w2 + (size_t)r * D);
    const float4* v4 = reinterpret_cast<const float4*>(g_h1);
    float acc = dot512(w4, v4, lane);
    if (lane == 0) out[r] = g_y[r] + acc + b2[r];
}

// ===========================================================================
extern "C" void kernel_launch(void* const* d_in, const int* in_sizes, int n_in,
                              void* d_out, int out_size) {
    const float* x     = (const float*)d_in[0];
    const float* w_in  = (const float*)d_in[1];
    const float* b_in  = (const float*)d_in[2];
    const float* w_out = (const float*)d_in[3];
    const float* b_out = (const float*)d_in[4];
    const float* w1    = (const float*)d_in[5];
    const float* b1    = (const float*)d_in[6];
    const float* w2    = (const float*)d_in[7];
    const float* b2    = (const float*)d_in[8];
    const float* g1    = (const float*)d_in[9];
    const float* be1   = (const float*)d_in[10];
    const float* g2    = (const float*)d_in[11];
    const float* be2   = (const float*)d_in[12];
    float* out = (float*)d_out;

    cudaFuncSetAttribute(k3_main, cudaFuncAttributeMaxDynamicSharedMemorySize, RING_BYTES);

    k1_q   <<<64, 256>>>(x, w_in, b_in, g1, be1);
    k2_u   <<<64, 256>>>(w_in, g1);
    k3_main<<<NB, K3_THREADS, RING_BYTES>>>(x);
    k4_z   <<<64, 512>>>(g1, be1);
    k5_ov  <<<64, 256>>>(w_in, b_in);
    k6_out <<<64, 256>>>(x, w_out, b_out);
    k7_mlp1<<<64, 256>>>(w1, b1, g2, be2);
    k8_mlp2<<<64, 256>>>(w2, b2, out);
}

// round 12
// speedup vs baseline: 1.5675x; 1.5675x over previous
#include <cuda_runtime.h>

#define Lseq 65536
#define D 512
#define H 4
#define HD 128
// scale * log2(e): scores computed in log2 domain, w = ex2(score)
#define SCALE2 (0.08838834764831845f * 1.4426950408889634f)

#define NB 148           // K3 blocks (1 per SM)
#define K3_THREADS 320
#define K3_WARPS 10
#define RING_BYTES (K3_WARPS*3*4096)   // 122880

typedef unsigned long long ull;

// ---------------- scratch (device globals; no allocation allowed) ----------
__device__ float g_q[D];
__device__ float g_ug[H*D];
__device__ float g_pse[H*NB];
__device__ float g_pam[H*NB];
__device__ float g_pzx[NB*H*D];
__device__ float g_z[H*D];
__device__ float g_opre[D];
__device__ float g_y[D];
__device__ float g_h1[D];

// ---------------- f32x2 packed helpers ------------------------------------
__device__ __forceinline__ ull pk2(float lo, float hi) {
    ull r; asm("mov.b64 %0,{%1,%2};" : "=l"(r) : "f"(lo), "f"(hi)); return r;
}
__device__ __forceinline__ void upk2(ull v, float& lo, float& hi) {
    asm("mov.b64 {%0,%1},%2;" : "=f"(lo), "=f"(hi) : "l"(v));
}
__device__ __forceinline__ ull fma2(ull a, ull b, ull c) {
    ull r; asm("fma.rn.f32x2 %0,%1,%2,%3;" : "=l"(r) : "l"(a), "l"(b), "l"(c)); return r;
}
__device__ __forceinline__ ull add2(ull a, ull b) {
    ull r; asm("add.rn.f32x2 %0,%1,%2;" : "=l"(r) : "l"(a), "l"(b)); return r;
}
__device__ __forceinline__ ull mul2(ull a, ull b) {
    ull r; asm("mul.rn.f32x2 %0,%1,%2;" : "=l"(r) : "l"(a), "l"(b)); return r;
}
__device__ __forceinline__ float ex2f(float x) {
    float y; asm("ex2.approx.f32 %0, %1;" : "=f"(y) : "f"(x)); return y;
}
// warp all-reduce via butterfly (redux.f32 does NOT exist on sm_103)
__device__ __forceinline__ float redux_add(float v) {
    #pragma unroll
    for (int o = 16; o; o >>= 1) v += __shfl_xor_sync(~0u, v, o);
    return v;
}

// ---------------- cp.async helpers ----------------------------------------
#define CPA(sa, ga) asm volatile("cp.async.cg.shared.global [%0], [%1], 16;" :: "r"(sa), "l"(ga))
#define CPC()       asm volatile("cp.async.commit_group;")
#define CPW(n)      asm volatile("cp.async.wait_group %0;" :: "n"(n))

// ---- warp GEMV: dot(w_row[0:512], v[0:512]) via float4 + butterfly --------
__device__ __forceinline__ float dot512(const float4* __restrict__ w4,
                                        const float4* __restrict__ v4, int lane) {
    float acc = 0.f;
    #pragma unroll
    for (int j = 0; j < 4; j++) {
        float4 w = w4[lane + 32*j];
        float4 s = v4[lane + 32*j];
        acc = fmaf(w.x, s.x, acc); acc = fmaf(w.y, s.y, acc);
        acc = fmaf(w.z, s.z, acc); acc = fmaf(w.w, s.w, acc);
    }
    return redux_add(acc);
}

// =================== K1: xn0 = LN(x[0]); q = Wq xn0 + bq ===================
__global__ void k1_q(const float* __restrict__ x, const float* __restrict__ w_in,
                     const float* __restrict__ b_in, const float* __restrict__ g1,
                     const float* __restrict__ be1) {
    int lane = threadIdx.x & 31;
    int r = blockIdx.x*8 + (threadIdx.x >> 5);
    const float4* x4 = reinterpret_cast<const float4*>(x);
    float4 xl[4]; float s1 = 0.f, s2 = 0.f;
    #pragma unroll
    for (int j = 0; j < 4; j++) {
        xl[j] = x4[lane + 32*j];
        s1 += xl[j].x + xl[j].y + xl[j].z + xl[j].w;
        s2 = fmaf(xl[j].x, xl[j].x, s2); s2 = fmaf(xl[j].y, xl[j].y, s2);
        s2 = fmaf(xl[j].z, xl[j].z, s2); s2 = fmaf(xl[j].w, xl[j].w, s2);
    }
    s1 = redux_add(s1); s2 = redux_add(s2);
    float mean = s1 * (1.f/D);
    float rstd = rsqrtf(s2 * (1.f/D) - mean*mean + 1e-5f);

    const float4* g14  = reinterpret_cast<const float4*>(g1);
    const float4* be14 = reinterpret_cast<const float4*>(be1);
    const float4* w4   = reinterpret_cast<const float4*>(w_in + (size_t)r * D);
    float acc = 0.f;
    #pragma unroll
    for (int j = 0; j < 4; j++) {
        float4 g = g14[lane + 32*j], b = be14[lane + 32*j], w = w4[lane + 32*j];
        float nx = (xl[j].x - mean)*rstd*g.x + b.x;
        float ny = (xl[j].y - mean)*rstd*g.y + b.y;
        float nz = (xl[j].z - mean)*rstd*g.z + b.z;
        float nw = (xl[j].w - mean)*rstd*g.w + b.w;
        acc = fmaf(w.x, nx, acc); acc = fmaf(w.y, ny, acc);
        acc = fmaf(w.z, nz, acc); acc = fmaf(w.w, nw, acc);
    }
    acc = redux_add(acc);
    if (lane == 0) g_q[r] = acc + b_in[r];
}

// ====== K2: ug[h*D+d] = SCALE2*g1[d]* (Wk_h^T q_h)[d]  (log2e folded) ======
__global__ void k2_u(const float* __restrict__ w_in, const float* __restrict__ g1) {
    __shared__ float red[8][32];
    __shared__ float qs[HD];
    int tid = threadIdx.x;
    int h  = blockIdx.x >> 4;
    int dc = blockIdx.x & 15;
    if (tid < HD) qs[tid] = g_q[h*HD + tid];
    __syncthreads();
    int c  = tid & 31;
    int ic = tid >> 5;
    int col = dc*32 + c;
    const float* wb = w_in + (size_t)(D + h*HD + ic*16) * D + col;
    float a0 = 0.f, a1 = 0.f, a2 = 0.f, a3 = 0.f;
    #pragma unroll
    for (int i = 0; i < 16; i += 4) {
        a0 = fmaf(wb[(size_t)(i+0) * D], qs[ic*16 + i+0], a0);
        a1 = fmaf(wb[(size_t)(i+1) * D], qs[ic*16 + i+1], a1);
        a2 = fmaf(wb[(size_t)(i+2) * D], qs[ic*16 + i+2], a2);
        a3 = fmaf(wb[(size_t)(i+3) * D], qs[ic*16 + i+3], a3);
    }
    red[ic][c] = (a0 + a1) + (a2 + a3);
    __syncthreads();
    if (tid < 32) {
        float s = 0.f;
        #pragma unroll
        for (int k = 0; k < 8; k++) s += red[k][tid];
        int d = dc*32 + tid;
        g_ug[h*D + d] = SCALE2 * g1[d] * s;
    }
}

// =================== K3: fused LN + scores + softmax + ZX ==================
// 10 warps/block (2.5/SMSP). Warp owns 45 rows (gw<416) else 44.
// Register-lean loop (no cross-iteration pipelining): update re-reads the
// tile from smem so pair registers don't stay live across the reduction.
// TLP (2.5 warps/SMSP) hides the reduce/MUFU chains instead of ILP.
__global__ void __launch_bounds__(K3_THREADS, 1)
k3_main(const float* __restrict__ x) {
    extern __shared__ __align__(16) float ring[];   // 10 warps * 3 slots * 1024 f
    __shared__ float sm_se[K3_WARPS][H], sm_am[K3_WARPS][H];

    int tid = threadIdx.x, lane = tid & 31, warp = tid >> 5;

    // ---- u into registers, center: u' = u - sug/D ----
    const float4* ug4 = reinterpret_cast<const float4*>(g_ug);
    ull u0[8], u1[8], u2[8], u3[8];
    {
        #pragma unroll
        for (int h = 0; h < 4; h++) {
            float acc = 0.f;
            #pragma unroll
            for (int j = 0; j < 4; j++) {
                float4 u = ug4[h*128 + lane + 32*j];
                ull plo = pk2(u.x, u.y), phi = pk2(u.z, u.w);
                if (h == 0) { u0[2*j] = plo; u0[2*j+1] = phi; }
                if (h == 1) { u1[2*j] = plo; u1[2*j+1] = phi; }
                if (h == 2) { u2[2*j] = plo; u2[2*j+1] = phi; }
                if (h == 3) { u3[2*j] = plo; u3[2*j+1] = phi; }
                acc += (u.x + u.y) + (u.z + u.w);
            }
            acc = redux_add(acc);
            float nm = -acc * (1.f/D);
            ull nm2 = pk2(nm, nm);
            #pragma unroll
            for (int k = 0; k < 8; k++) {
                if (h == 0) u0[k] = add2(u0[k], nm2);
                if (h == 1) u1[k] = add2(u1[k], nm2);
                if (h == 2) u2[k] = add2(u2[k], nm2);
                if (h == 3) u3[k] = add2(u3[k], nm2);
            }
        }
    }

    float se0 = 0.f, se1 = 0.f, se2 = 0.f, se3 = 0.f;
    float am0 = 0.f, am1 = 0.f, am2 = 0.f, am3 = 0.f;
    ull zx0[8], zx1[8], zx2[8], zx3[8];
    #pragma unroll
    for (int k = 0; k < 8; k++) { zx0[k]=0ull; zx1[k]=0ull; zx2[k]=0ull; zx3[k]=0ull; }

    const float4* xb = reinterpret_cast<const float4*>(x);
    int gw = blockIdx.x * K3_WARPS + warp;            // 0..1479
    int start = gw*44 + (gw < 416 ? gw : 416);        // 65536 = 416*45 + 1064*44
    int cnt   = 44 + (gw < 416 ? 1 : 0);
    int npairs = (cnt + 1) >> 1;                      // 23 or 22

    unsigned warp_base = (unsigned)__cvta_generic_to_shared(ring) + warp * 3 * 4096;
    bool lowh = (lane & 16) == 0;

    auto refill = [&](int q, int slotn) {
        #pragma unroll
        for (int rr = 0; rr < 2; rr++) {
            int l = start + 2*q + rr;
            if (l > start + cnt - 1) l = start;     // masked row: safe addr
            unsigned sa = warp_base + slotn*4096 + rr*2048 + lane*16;
            const float4* g = xb + (size_t)l * 128 + lane;
            CPA(sa,       g);
            CPA(sa+32*16, g+32);
            CPA(sa+64*16, g+64);
            CPA(sa+96*16, g+96);
        }
    };
    auto ldpair = [&](int slotn, ull* A, ull* B) {
        const ulonglong2* s8 = reinterpret_cast<const ulonglong2*>(ring + warp*3072 + slotn*1024);
        ulonglong2 t;
        t = s8[lane];      A[0]=t.x; A[1]=t.y;
        t = s8[lane+32];   A[2]=t.x; A[3]=t.y;
        t = s8[lane+64];   A[4]=t.x; A[5]=t.y;
        t = s8[lane+96];   A[6]=t.x; A[7]=t.y;
        t = s8[lane+128];  B[0]=t.x; B[1]=t.y;
        t = s8[lane+160];  B[2]=t.x; B[3]=t.y;
        t = s8[lane+192];  B[4]=t.x; B[5]=t.y;
        t = s8[lane+224];  B[6]=t.x; B[7]=t.y;
    };
    // P layout: [s1a,s2a,e0a,e1a,e2a,e3a, s1b,s2b,e0b,e1b,e2b,e3b]
    auto partials = [&](const ull* A, const ull* B, float* P) {
        ull spA = A[0], qpA = mul2(A[0], A[0]);
        ull spB = B[0], qpB = mul2(B[0], B[0]);
        #pragma unroll
        for (int i = 1; i < 8; i++) {
            spA = add2(spA, A[i]); qpA = fma2(A[i], A[i], qpA);
            spB = add2(spB, B[i]); qpB = fma2(B[i], B[i], qpB);
        }
        ull d0A=0, d1A=0, d2A=0, d3A=0, d0B=0, d1B=0, d2B=0, d3B=0;
        #pragma unroll
        for (int k = 0; k < 8; k++) {
            d0A = fma2(A[k], u0[k], d0A); d0B = fma2(B[k], u0[k], d0B);
            d1A = fma2(A[k], u1[k], d1A); d1B = fma2(B[k], u1[k], d1B);
            d2A = fma2(A[k], u2[k], d2A); d2B = fma2(B[k], u2[k], d2B);
            d3A = fma2(A[k], u3[k], d3A); d3B = fma2(B[k], u3[k], d3B);
        }
        float t0, t1;
        upk2(spA,t0,t1); P[0] = t0+t1;  upk2(qpA,t0,t1); P[1] = t0+t1;
        upk2(d0A,t0,t1); P[2] = t0+t1;  upk2(d1A,t0,t1); P[3] = t0+t1;
        upk2(d2A,t0,t1); P[4] = t0+t1;  upk2(d3A,t0,t1); P[5] = t0+t1;
        upk2(spB,t0,t1); P[6] = t0+t1;  upk2(qpB,t0,t1); P[7] = t0+t1;
        upk2(d0B,t0,t1); P[8] = t0+t1;  upk2(d1B,t0,t1); P[9] = t0+t1;
        upk2(d2B,t0,t1); P[10]= t0+t1;  upk2(d3B,t0,t1); P[11]= t0+t1;
    };
    // half-split 12-value all-reduce: 42 SHFL + 36 FADD (vs 60/60 naive)
    auto reduce12 = [&](float* P) {
        #pragma unroll
        for (int k = 0; k < 12; k++) P[k] += __shfl_xor_sync(~0u, P[k], 16);
        float q[6];
        #pragma unroll
        for (int j = 0; j < 6; j++) q[j] = lowh ? P[2*j] : P[2*j+1];
        #pragma unroll
        for (int o = 8; o; o >>= 1) {
            #pragma unroll
            for (int j = 0; j < 6; j++) q[j] += __shfl_xor_sync(~0u, q[j], o);
        }
        #pragma unroll
        for (int j = 0; j < 6; j++) {
            float r = __shfl_xor_sync(~0u, q[j], 16);
            P[2*j]   = lowh ? q[j] : r;
            P[2*j+1] = lowh ? r : q[j];
        }
    };
    // update: re-reads the tile from smem (keeps pair regs transient)
    auto update2 = [&](int slotn, const float* P, float validB) {
        ull A[8], B[8];
        ldpair(slotn, A, B);
        {   // row A
            float mean = P[0] * (1.f/D);
            float rstd = rsqrtf(P[1] * (1.f/D) - mean*mean + 1e-5f);
            float w0 = ex2f(rstd * P[2]);
            float w1 = ex2f(rstd * P[3]);
            float w2 = ex2f(rstd * P[4]);
            float w3 = ex2f(rstd * P[5]);
            se0 += w0; se1 += w1; se2 += w2; se3 += w3;
            float wr0 = w0*rstd, wr1 = w1*rstd, wr2 = w2*rstd, wr3 = w3*rstd;
            am0 = fmaf(wr0, mean, am0); am1 = fmaf(wr1, mean, am1);
            am2 = fmaf(wr2, mean, am2); am3 = fmaf(wr3, mean, am3);
            ull p0 = pk2(wr0,wr0), p1 = pk2(wr1,wr1), p2 = pk2(wr2,wr2), p3 = pk2(wr3,wr3);
            #pragma unroll
            for (int k = 0; k < 8; k++) {
                zx0[k] = fma2(A[k], p0, zx0[k]);
                zx1[k] = fma2(A[k], p1, zx1[k]);
                zx2[k] = fma2(A[k], p2, zx2[k]);
                zx3[k] = fma2(A[k], p3, zx3[k]);
            }
        }
        {   // row B (masked on last pair of odd-count chunks)
            float mean = P[6] * (1.f/D);
            float rstd = rsqrtf(P[7] * (1.f/D) - mean*mean + 1e-5f);
            float w0 = validB * ex2f(rstd * P[8]);
            float w1 = validB * ex2f(rstd * P[9]);
            float w2 = validB * ex2f(rstd * P[10]);
            float w3 = validB * ex2f(rstd * P[11]);
            se0 += w0; se1 += w1; se2 += w2; se3 += w3;
            float wr0 = w0*rstd, wr1 = w1*rstd, wr2 = w2*rstd, wr3 = w3*rstd;
            am0 = fmaf(wr0, mean, am0); am1 = fmaf(wr1, mean, am1);
            am2 = fmaf(wr2, mean, am2); am3 = fmaf(wr3, mean, am3);
            ull p0 = pk2(wr0,wr0), p1 = pk2(wr1,wr1), p2 = pk2(wr2,wr2), p3 = pk2(wr3,wr3);
            #pragma unroll
            for (int k = 0; k < 8; k++) {
                zx0[k] = fma2(B[k], p0, zx0[k]);
                zx1[k] = fma2(B[k], p1, zx1[k]);
                zx2[k] = fma2(B[k], p2, zx2[k]);
                zx3[k] = fma2(B[k], p3, zx3[k]);
            }
        }
    };

    // ---- prologue: prefetch pairs 0..2 ----
    #pragma unroll
    for (int pp = 0; pp < 3; pp++) { refill(pp, pp); CPC(); }

    #pragma unroll 3
    for (int p = 0; p < npairs; p++) {
        int slot = p % 3;
        CPW(2);
        float cp[12];
        {
            ull A[8], B[8];
            ldpair(slot, A, B);
            partials(A, B, cp);
        }
        reduce12(cp);
        float validB = (2*p + 1 < cnt) ? 1.f : 0.f;
        update2(slot, cp, validB);
        if (p + 3 < npairs) refill(p + 3, slot);
        CPC();
    }

    // ---- block combine (se/am are warp-uniform) ----
    if (lane == 0) {
        sm_se[warp][0]=se0; sm_se[warp][1]=se1; sm_se[warp][2]=se2; sm_se[warp][3]=se3;
        sm_am[warp][0]=am0; sm_am[warp][1]=am1; sm_am[warp][2]=am2; sm_am[warp][3]=am3;
    }
    // ---- stage zx into (now dead) ring smem: warp w owns ring[w*2048..] ----
    CPW(0);
    __syncthreads();     // all warps done with ring slots AND sm_se/sm_am written
    if (tid < H) {
        int h = tid;
        float bse = 0.f, bam = 0.f;
        #pragma unroll
        for (int w = 0; w < K3_WARPS; w++) { bse += sm_se[w][h]; bam += sm_am[w][h]; }
        g_pse[h*NB + blockIdx.x] = bse;
        g_pam[h*NB + blockIdx.x] = bam;
    }
    {
        float z0[16], z1[16], z2[16], z3[16];
        #pragma unroll
        for (int k = 0; k < 8; k++) {
            upk2(zx0[k], z0[2*k], z0[2*k+1]);
            upk2(zx1[k], z1[2*k], z1[2*k+1]);
            upk2(zx2[k], z2[2*k], z2[2*k+1]);
            upk2(zx3[k], z3[2*k], z3[2*k+1]);
        }
        float* wb = ring + warp*2048;
        #pragma unroll
        for (int j = 0; j < 4; j++) {
            *reinterpret_cast<float4*>(wb + 0*512 + j*128 + 4*lane) =
                make_float4(z0[4*j], z0[4*j+1], z0[4*j+2], z0[4*j+3]);
            *reinterpret_cast<float4*>(wb + 1*512 + j*128 + 4*lane) =
                make_float4(z1[4*j], z1[4*j+1], z1[4*j+2], z1[4*j+3]);
            *reinterpret_cast<float4*>(wb + 2*512 + j*128 + 4*lane) =
                make_float4(z2[4*j], z2[4*j+1], z2[4*j+2], z2[4*j+3]);
            *reinterpret_cast<float4*>(wb + 3*512 + j*128 + 4*lane) =
                make_float4(z3[4*j], z3[4*j+1], z3[4*j+2], z3[4*j+3]);
        }
    }
    __syncthreads();
    // ---- tree-reduce 10 warp copies -> g_pzx (dense float4, no conflicts) --
    for (int idx = tid; idx < 512; idx += K3_THREADS) {
        float4 a = make_float4(0.f,0.f,0.f,0.f);
        #pragma unroll
        for (int w = 0; w < K3_WARPS; w++) {
            float4 v = *reinterpret_cast<const float4*>(ring + w*2048 + 4*idx);
            a.x += v.x; a.y += v.y; a.z += v.z; a.w += v.w;
        }
        reinterpret_cast<float4*>(g_pzx + (size_t)blockIdx.x*(H*D))[idx] = a;
    }
}

// ======== K4: z = g1*(sum_b ZX - AM)/SE + be1 (plain sums) =================
// grid 64 = (h:4, dchunk:16 of 32 cols), 512 threads (16 warps, high MLP)
__global__ void __launch_bounds__(512, 2)
k4_z(const float* __restrict__ g1, const float* __restrict__ be1) {
    int h = blockIdx.x >> 4;
    int dbase = (blockIdx.x & 15) * 32;
    int tid = threadIdx.x, lane = tid & 31, warp = tid >> 5;
    __shared__ float part[16][32];
    __shared__ float sSE, sAM;

    if (warp == 0) {
        float se = 0.f;
        #pragma unroll
        for (int b = lane; b < NB; b += 32) se += g_pse[h*NB + b];
        se = redux_add(se);
        if (lane == 0) sSE = se;
    } else if (warp == 1) {
        float am = 0.f;
        #pragma unroll
        for (int b = lane; b < NB; b += 32) am += g_pam[h*NB + b];
        am = redux_add(am);
        if (lane == 0) sAM = am;
    }

    float acc = 0.f;
    int b0 = warp * 10;
    int be = b0 + 10 < NB ? b0 + 10 : NB;
    #pragma unroll 5
    for (int b = b0; b < be; b++)
        acc += g_pzx[(size_t)b*(H*D) + h*D + dbase + lane];
    part[warp][lane] = acc;
    __syncthreads();
    if (warp == 0) {
        float s = part[0][lane];
        #pragma unroll
        for (int w = 1; w < 16; w++) s += part[w][lane];
        int d = dbase + lane;
        g_z[h*D + d] = g1[d] * (s - sAM) / sSE + be1[d];
    }
}

// ========= K5: o_pre[r] = dot(Wv[r], z_{head(r)}) + bv[r]  (warp per row) ==
__global__ void k5_ov(const float* __restrict__ w_in, const float* __restrict__ b_in) {
    int lane = threadIdx.x & 31;
    int r = blockIdx.x*8 + (threadIdx.x >> 5);
    const float4* w4 = reinterpret_cast<const float4*>(w_in + (size_t)(2*D + r) * D);
    const float4* v4 = reinterpret_cast<const float4*>(g_z + (r >> 7) * D);
    float acc = dot512(w4, v4, lane);
    if (lane == 0) g_opre[r] = acc + b_in[2*D + r];
}

// ========= K6: y = x[0] + w_out @ o_pre + b_out  (warp per row) ============
__global__ void k6_out(const float* __restrict__ x, const float* __restrict__ w_out,
                       const float* __restrict__ b_out) {
    int lane = threadIdx.x & 31;
    int r = blockIdx.x*8 + (threadIdx.x >> 5);
    const float4* w4 = reinterpret_cast<const float4*>(w_out + (size_t)r * D);
    const float4* v4 = reinterpret_cast<const float4*>(g_opre);
    float acc = dot512(w4, v4, lane);
    if (lane == 0) g_y[r] = x[r] + acc + b_out[r];
}

// ========= K7: h1 = relu(LN(y,g2,be2) @ w1^T + b1)  (warp per row) =========
__global__ void k7_mlp1(const float* __restrict__ w1, const float* __restrict__ b1,
                        const float* __restrict__ g2, const float* __restrict__ be2) {
    int lane = threadIdx.x & 31;
    int r = blockIdx.x*8 + (threadIdx.x >> 5);
    const float4* y4 = reinterpret_cast<const float4*>(g_y);
    float4 yl[4]; float s1 = 0.f, s2 = 0.f;
    #pragma unroll
    for (int j = 0; j < 4; j++) {
        yl[j] = y4[lane + 32*j];
        s1 += yl[j].x + yl[j].y + yl[j].z + yl[j].w;
        s2 = fmaf(yl[j].x, yl[j].x, s2); s2 = fmaf(yl[j].y, yl[j].y, s2);
        s2 = fmaf(yl[j].z, yl[j].z, s2); s2 = fmaf(yl[j].w, yl[j].w, s2);
    }
    s1 = redux_add(s1); s2 = redux_add(s2);
    float mean = s1 * (1.f/D);
    float rstd = rsqrtf(s2 * (1.f/D) - mean*mean + 1e-5f);

    const float4* g24  = reinterpret_cast<const float4*>(g2);
    const float4* be24 = reinterpret_cast<const float4*>(be2);
    const float4* w4   = reinterpret_cast<const float4*>(w1 + (size_t)r * D);
    float acc = 0.f;
    #pragma unroll
    for (int j = 0; j < 4; j++) {
        float4 g = g24[lane + 32*j], b = be24[lane + 32*j], w = w4[lane + 32*j];
        float nx = (yl[j].x - mean)*rstd*g.x + b.x;
        float ny = (yl[j].y - mean)*rstd*g.y + b.y;
        float nz = (yl[j].z - mean)*rstd*g.z + b.z;
        float nw = (yl[j].w - mean)*rstd*g.w + b.w;
        acc = fmaf(w.x, nx, acc); acc = fmaf(w.y, ny, acc);
        acc = fmaf(w.z, nz, acc); acc = fmaf(w.w, nw, acc);
    }
    acc = redux_add(acc);
    if (lane == 0) g_h1[r] = fmaxf(acc + b1[r], 0.f);
}

// ========= K8: out = y + w2 @ h1 + b2  (warp per row) ======================
__global__ void k8_mlp2(const float* __restrict__ w2, const float* __restrict__ b2,
                        float* __restrict__ out) {
    int lane = threadIdx.x & 31;
    int r = blockIdx.x*8 + (threadIdx.x >> 5);
    const float4* w4 = reinterpret_cast<const float4*>(w2 + (size_t)r * D);
    const float4* v4 = reinterpret_cast<const float4*>(g_h1);
    float acc = dot512(w4, v4, lane);
    if (lane == 0) out[r] = g_y[r] + acc + b2[r];
}

// ===========================================================================
extern "C" void kernel_launch(void* const* d_in, const int* in_sizes, int n_in,
                              void* d_out, int out_size) {
    const float* x     = (const float*)d_in[0];
    const float* w_in  = (const float*)d_in[1];
    const float* b_in  = (const float*)d_in[2];
    const float* w_out = (const float*)d_in[3];
    const float* b_out = (const float*)d_in[4];
    const float* w1    = (const float*)d_in[5];
    const float* b1    = (const float*)d_in[6];
    const float* w2    = (const float*)d_in[7];
    const float* b2    = (const float*)d_in[8];
    const float* g1    = (const float*)d_in[9];
    const float* be1   = (const float*)d_in[10];
    const float* g2    = (const float*)d_in[11];
    const float* be2   = (const float*)d_in[12];
    float* out = (float*)d_out;

    cudaFuncSetAttribute(k3_main, cudaFuncAttributeMaxDynamicSharedMemorySize, RING_BYTES);

    k1_q   <<<64, 256>>>(x, w_in, b_in, g1, be1);
    k2_u   <<<64, 256>>>(w_in, g1);
    k3_main<<<NB, K3_THREADS, RING_BYTES>>>(x);
    k4_z   <<<64, 512>>>(g1, be1);
    k5_ov  <<<64, 256>>>(w_in, b_in);
    k6_out <<<64, 256>>>(x, w_out, b_out);
    k7_mlp1<<<64, 256>>>(w1, b1, g2, be2);
    k8_mlp2<<<64, 256>>>(w2, b2, out);
}

// round 13
// speedup vs baseline: 2.1997x; 1.4034x over previous
#include <cuda_runtime.h>

#define Lseq 65536
#define D 512
#define H 4
#define HD 128
// scale * log2(e): scores computed in log2 domain, w = ex2(score)
#define SCALE2 (0.08838834764831845f * 1.4426950408889634f)

#define NB 148           // K3 blocks (1 per SM)
#define K3_THREADS 256
#define K3_WARPS 8

typedef unsigned long long ull;

// ---------------- scratch (device globals; no allocation allowed) ----------
__device__ float g_q[D];
__device__ float g_ug[H*D];
__device__ float g_pse[H*NB];
__device__ float g_pam[H*NB];
__device__ float g_pzx[NB*H*D];
__device__ float g_z[H*D];
__device__ float g_opre[D];
__device__ float g_y[D];
__device__ float g_h1[D];
__device__ int   g_bar1;   // zero-init; self-resetting
__device__ int   g_bar2;   // zero-init; self-resetting

// ---------------- f32x2 packed helpers ------------------------------------
__device__ __forceinline__ ull pk2(float lo, float hi) {
    ull r; asm("mov.b64 %0,{%1,%2};" : "=l"(r) : "f"(lo), "f"(hi)); return r;
}
__device__ __forceinline__ void upk2(ull v, float& lo, float& hi) {
    asm("mov.b64 {%0,%1},%2;" : "=f"(lo), "=f"(hi) : "l"(v));
}
__device__ __forceinline__ ull fma2(ull a, ull b, ull c) {
    ull r; asm("fma.rn.f32x2 %0,%1,%2,%3;" : "=l"(r) : "l"(a), "l"(b), "l"(c)); return r;
}
__device__ __forceinline__ ull add2(ull a, ull b) {
    ull r; asm("add.rn.f32x2 %0,%1,%2;" : "=l"(r) : "l"(a), "l"(b)); return r;
}
__device__ __forceinline__ ull mul2(ull a, ull b) {
    ull r; asm("mul.rn.f32x2 %0,%1,%2;" : "=l"(r) : "l"(a), "l"(b)); return r;
}
__device__ __forceinline__ float ex2f(float x) {
    float y; asm("ex2.approx.f32 %0, %1;" : "=f"(y) : "f"(x)); return y;
}
__device__ __forceinline__ float rsq(float x) {
    float y; asm("rsqrt.approx.f32 %0, %1;" : "=f"(y) : "f"(x)); return y;
}
// warp all-reduce via butterfly (redux.f32 does NOT exist on sm_103)
__device__ __forceinline__ float redux_add(float v) {
    #pragma unroll
    for (int o = 16; o; o >>= 1) v += __shfl_xor_sync(~0u, v, o);
    return v;
}

// ---------------- device-wide barrier (all blocks co-resident) -------------
__device__ __forceinline__ void gbar(int* cnt, int target) {
    __syncthreads();
    if (threadIdx.x == 0) {
        __threadfence();
        atomicAdd(cnt, 1);
        while (*(volatile int*)cnt < target) { }
        __threadfence();
    }
    __syncthreads();
}
// final arrive: last block resets the counter for the next graph replay.
// Safe: by the time the last arrival happens, every block has already exited
// every earlier spin loop (final arrivals come after the last barrier).
__device__ __forceinline__ void gbar_final(int* cnt, int total) {
    __syncthreads();
    if (threadIdx.x == 0) {
        __threadfence();
        int t = atomicAdd(cnt, 1);
        if (t == total - 1) *(volatile int*)cnt = 0;
    }
}

// ---------------- cp.async helpers ----------------------------------------
#define CPA(sa, ga) asm volatile("cp.async.cg.shared.global [%0], [%1], 16;" :: "r"(sa), "l"(ga))
#define CPC()       asm volatile("cp.async.commit_group;")
#define CPW(n)      asm volatile("cp.async.wait_group %0;" :: "n"(n))

// ---- warp GEMV: dot(w_row[0:512], v[0:512]) via float4 + butterfly --------
__device__ __forceinline__ float dot512(const float4* __restrict__ w4,
                                        const float4* __restrict__ v4, int lane) {
    float acc = 0.f;
    #pragma unroll
    for (int j = 0; j < 4; j++) {
        float4 w = w4[lane + 32*j];
        float4 s = v4[lane + 32*j];
        acc = fmaf(w.x, s.x, acc); acc = fmaf(w.y, s.y, acc);
        acc = fmaf(w.z, s.z, acc); acc = fmaf(w.w, s.w, acc);
    }
    return redux_add(acc);
}

// ========= K12: phase1 q = Wq LN(x0) + bq;  barrier;  phase2 ug ============
// grid 64 x 256
__global__ void k12(const float* __restrict__ x, const float* __restrict__ w_in,
                    const float* __restrict__ b_in, const float* __restrict__ g1,
                    const float* __restrict__ be1) {
    __shared__ float qs[HD];
    __shared__ float red[8][32];
    int tid = threadIdx.x, lane = tid & 31, warp = tid >> 5;

    // ---- phase 1: q rows b*8+warp ----
    {
        int r = blockIdx.x*8 + warp;
        const float4* x4 = reinterpret_cast<const float4*>(x);
        float4 xl[4]; float s1 = 0.f, s2 = 0.f;
        #pragma unroll
        for (int j = 0; j < 4; j++) {
            xl[j] = x4[lane + 32*j];
            s1 += xl[j].x + xl[j].y + xl[j].z + xl[j].w;
            s2 = fmaf(xl[j].x, xl[j].x, s2); s2 = fmaf(xl[j].y, xl[j].y, s2);
            s2 = fmaf(xl[j].z, xl[j].z, s2); s2 = fmaf(xl[j].w, xl[j].w, s2);
        }
        s1 = redux_add(s1); s2 = redux_add(s2);
        float mean = s1 * (1.f/D);
        float rstd = rsq(s2 * (1.f/D) - mean*mean + 1e-5f);

        const float4* g14  = reinterpret_cast<const float4*>(g1);
        const float4* be14 = reinterpret_cast<const float4*>(be1);
        const float4* w4   = reinterpret_cast<const float4*>(w_in + (size_t)r * D);
        float acc = 0.f;
        #pragma unroll
        for (int j = 0; j < 4; j++) {
            float4 g = g14[lane + 32*j], b = be14[lane + 32*j], w = w4[lane + 32*j];
            float nx = (xl[j].x - mean)*rstd*g.x + b.x;
            float ny = (xl[j].y - mean)*rstd*g.y + b.y;
            float nz = (xl[j].z - mean)*rstd*g.z + b.z;
            float nw = (xl[j].w - mean)*rstd*g.w + b.w;
            acc = fmaf(w.x, nx, acc); acc = fmaf(w.y, ny, acc);
            acc = fmaf(w.z, nz, acc); acc = fmaf(w.w, nw, acc);
        }
        acc = redux_add(acc);
        if (lane == 0) g_q[r] = acc + b_in[r];
    }

    gbar(&g_bar1, 64);

    // ---- phase 2: ug[h*D+d] = SCALE2*g1[d]*(Wk_h^T q_h)[d] ----
    {
        int h  = blockIdx.x >> 4;
        int dc = blockIdx.x & 15;
        if (tid < HD) qs[tid] = g_q[h*HD + tid];
        __syncthreads();
        int c  = tid & 31;
        int ic = tid >> 5;
        int col = dc*32 + c;
        const float* wb = w_in + (size_t)(D + h*HD + ic*16) * D + col;
        float a0 = 0.f, a1 = 0.f, a2 = 0.f, a3 = 0.f;
        #pragma unroll
        for (int i = 0; i < 16; i += 4) {
            a0 = fmaf(wb[(size_t)(i+0) * D], qs[ic*16 + i+0], a0);
            a1 = fmaf(wb[(size_t)(i+1) * D], qs[ic*16 + i+1], a1);
            a2 = fmaf(wb[(size_t)(i+2) * D], qs[ic*16 + i+2], a2);
            a3 = fmaf(wb[(size_t)(i+3) * D], qs[ic*16 + i+3], a3);
        }
        red[ic][c] = (a0 + a1) + (a2 + a3);
        __syncthreads();
        if (tid < 32) {
            float s = 0.f;
            #pragma unroll
            for (int k = 0; k < 8; k++) s += red[k][tid];
            int d = dc*32 + tid;
            g_ug[h*D + d] = SCALE2 * g1[d] * s;
        }
    }

    gbar_final(&g_bar1, 128);
}

// =================== K3: fused LN + scores + softmax + ZX ==================
// (unchanged from the 49.7us champion, rsqrtf -> rsqrt.approx)
__global__ void __launch_bounds__(K3_THREADS, 1)
k3_main(const float* __restrict__ x) {
    extern __shared__ __align__(16) float ring[];   // 8 warps * 3 slots * 1024 f = 96KB
    __shared__ float sm_se[K3_WARPS][H], sm_am[K3_WARPS][H];

    int tid = threadIdx.x, lane = tid & 31, warp = tid >> 5;

    // ---- u into registers, center: u' = u - sug/D ----
    const float4* ug4 = reinterpret_cast<const float4*>(g_ug);
    ull u0[8], u1[8], u2[8], u3[8];
    {
        #pragma unroll
        for (int h = 0; h < 4; h++) {
            float acc = 0.f;
            #pragma unroll
            for (int j = 0; j < 4; j++) {
                float4 u = ug4[h*128 + lane + 32*j];
                ull plo = pk2(u.x, u.y), phi = pk2(u.z, u.w);
                if (h == 0) { u0[2*j] = plo; u0[2*j+1] = phi; }
                if (h == 1) { u1[2*j] = plo; u1[2*j+1] = phi; }
                if (h == 2) { u2[2*j] = plo; u2[2*j+1] = phi; }
                if (h == 3) { u3[2*j] = plo; u3[2*j+1] = phi; }
                acc += (u.x + u.y) + (u.z + u.w);
            }
            acc = redux_add(acc);
            float nm = -acc * (1.f/D);
            ull nm2 = pk2(nm, nm);
            #pragma unroll
            for (int k = 0; k < 8; k++) {
                if (h == 0) u0[k] = add2(u0[k], nm2);
                if (h == 1) u1[k] = add2(u1[k], nm2);
                if (h == 2) u2[k] = add2(u2[k], nm2);
                if (h == 3) u3[k] = add2(u3[k], nm2);
            }
        }
    }

    float se0 = 0.f, se1 = 0.f, se2 = 0.f, se3 = 0.f;
    float am0 = 0.f, am1 = 0.f, am2 = 0.f, am3 = 0.f;
    ull zx0[8], zx1[8], zx2[8], zx3[8];
    #pragma unroll
    for (int k = 0; k < 8; k++) { zx0[k]=0ull; zx1[k]=0ull; zx2[k]=0ull; zx3[k]=0ull; }

    const float4* xb = reinterpret_cast<const float4*>(x);
    int gw = blockIdx.x * K3_WARPS + warp;
    int start = gw*55 + (gw < 416 ? gw : 416);
    int cnt   = gw < 416 ? 56 : 55;

    unsigned warp_base = (unsigned)__cvta_generic_to_shared(ring) + warp * 3 * 4096;
    bool lowh = (lane & 16) == 0;

    auto refill = [&](int q, int slotn) {
        #pragma unroll
        for (int rr = 0; rr < 2; rr++) {
            int l = start + 2*q + rr;
            if (l > start + cnt - 1) l = start;     // masked row: safe addr
            unsigned sa = warp_base + slotn*4096 + rr*2048 + lane*16;
            const float4* g = xb + (size_t)l * 128 + lane;
            CPA(sa,       g);
            CPA(sa+32*16, g+32);
            CPA(sa+64*16, g+64);
            CPA(sa+96*16, g+96);
        }
    };
    auto ldpair = [&](int slotn, ull* A, ull* B) {
        const ulonglong2* s8 = reinterpret_cast<const ulonglong2*>(ring + warp*3072 + slotn*1024);
        ulonglong2 t;
        t = s8[lane];      A[0]=t.x; A[1]=t.y;
        t = s8[lane+32];   A[2]=t.x; A[3]=t.y;
        t = s8[lane+64];   A[4]=t.x; A[5]=t.y;
        t = s8[lane+96];   A[6]=t.x; A[7]=t.y;
        t = s8[lane+128];  B[0]=t.x; B[1]=t.y;
        t = s8[lane+160];  B[2]=t.x; B[3]=t.y;
        t = s8[lane+192];  B[4]=t.x; B[5]=t.y;
        t = s8[lane+224];  B[6]=t.x; B[7]=t.y;
    };
    // P layout: [s1a,s2a,e0a,e1a,e2a,e3a, s1b,s2b,e0b,e1b,e2b,e3b]
    auto partials = [&](const ull* A, const ull* B, float* P) {
        ull spA = A[0], qpA = mul2(A[0], A[0]);
        ull spB = B[0], qpB = mul2(B[0], B[0]);
        #pragma unroll
        for (int i = 1; i < 8; i++) {
            spA = add2(spA, A[i]); qpA = fma2(A[i], A[i], qpA);
            spB = add2(spB, B[i]); qpB = fma2(B[i], B[i], qpB);
        }
        ull d0A=0, d1A=0, d2A=0, d3A=0, d0B=0, d1B=0, d2B=0, d3B=0;
        #pragma unroll
        for (int k = 0; k < 8; k++) {
            d0A = fma2(A[k], u0[k], d0A); d0B = fma2(B[k], u0[k], d0B);
            d1A = fma2(A[k], u1[k], d1A); d1B = fma2(B[k], u1[k], d1B);
            d2A = fma2(A[k], u2[k], d2A); d2B = fma2(B[k], u2[k], d2B);
            d3A = fma2(A[k], u3[k], d3A); d3B = fma2(B[k], u3[k], d3B);
        }
        float t0, t1;
        upk2(spA,t0,t1); P[0] = t0+t1;  upk2(qpA,t0,t1); P[1] = t0+t1;
        upk2(d0A,t0,t1); P[2] = t0+t1;  upk2(d1A,t0,t1); P[3] = t0+t1;
        upk2(d2A,t0,t1); P[4] = t0+t1;  upk2(d3A,t0,t1); P[5] = t0+t1;
        upk2(spB,t0,t1); P[6] = t0+t1;  upk2(qpB,t0,t1); P[7] = t0+t1;
        upk2(d0B,t0,t1); P[8] = t0+t1;  upk2(d1B,t0,t1); P[9] = t0+t1;
        upk2(d2B,t0,t1); P[10]= t0+t1;  upk2(d3B,t0,t1); P[11]= t0+t1;
    };
    // half-split 12-value all-reduce: 42 SHFL + 36 FADD (vs 60/60 naive)
    auto reduce12 = [&](float* P) {
        #pragma unroll
        for (int k = 0; k < 12; k++) P[k] += __shfl_xor_sync(~0u, P[k], 16);
        float q[6];
        #pragma unroll
        for (int j = 0; j < 6; j++) q[j] = lowh ? P[2*j] : P[2*j+1];
        #pragma unroll
        for (int o = 8; o; o >>= 1) {
            #pragma unroll
            for (int j = 0; j < 6; j++) q[j] += __shfl_xor_sync(~0u, q[j], o);
        }
        #pragma unroll
        for (int j = 0; j < 6; j++) {
            float r = __shfl_xor_sync(~0u, q[j], 16);
            P[2*j]   = lowh ? q[j] : r;
            P[2*j+1] = lowh ? r : q[j];
        }
    };
    auto update = [&](const float* P, const ull* A, const ull* B, float validB) {
        {   // row A
            float mean = P[0] * (1.f/D);
            float rstd = rsq(P[1] * (1.f/D) - mean*mean + 1e-5f);
            float w0 = ex2f(rstd * P[2]);
            float w1 = ex2f(rstd * P[3]);
            float w2 = ex2f(rstd * P[4]);
            float w3 = ex2f(rstd * P[5]);
            se0 += w0; se1 += w1; se2 += w2; se3 += w3;
            float wr0 = w0*rstd, wr1 = w1*rstd, wr2 = w2*rstd, wr3 = w3*rstd;
            am0 = fmaf(wr0, mean, am0); am1 = fmaf(wr1, mean, am1);
            am2 = fmaf(wr2, mean, am2); am3 = fmaf(wr3, mean, am3);
            ull p0 = pk2(wr0,wr0), p1 = pk2(wr1,wr1), p2 = pk2(wr2,wr2), p3 = pk2(wr3,wr3);
            #pragma unroll
            for (int k = 0; k < 8; k++) {
                zx0[k] = fma2(A[k], p0, zx0[k]);
                zx1[k] = fma2(A[k], p1, zx1[k]);
                zx2[k] = fma2(A[k], p2, zx2[k]);
                zx3[k] = fma2(A[k], p3, zx3[k]);
            }
        }
        {   // row B (masked on last pair of 55-row chunks)
            float mean = P[6] * (1.f/D);
            float rstd = rsq(P[7] * (1.f/D) - mean*mean + 1e-5f);
            float w0 = validB * ex2f(rstd * P[8]);
            float w1 = validB * ex2f(rstd * P[9]);
            float w2 = validB * ex2f(rstd * P[10]);
            float w3 = validB * ex2f(rstd * P[11]);
            se0 += w0; se1 += w1; se2 += w2; se3 += w3;
            float wr0 = w0*rstd, wr1 = w1*rstd, wr2 = w2*rstd, wr3 = w3*rstd;
            am0 = fmaf(wr0, mean, am0); am1 = fmaf(wr1, mean, am1);
            am2 = fmaf(wr2, mean, am2); am3 = fmaf(wr3, mean, am3);
            ull p0 = pk2(wr0,wr0), p1 = pk2(wr1,wr1), p2 = pk2(wr2,wr2), p3 = pk2(wr3,wr3);
            #pragma unroll
            for (int k = 0; k < 8; k++) {
                zx0[k] = fma2(B[k], p0, zx0[k]);
                zx1[k] = fma2(B[k], p1, zx1[k]);
                zx2[k] = fma2(B[k], p2, zx2[k]);
                zx3[k] = fma2(B[k], p3, zx3[k]);
            }
        }
    };

    // ---- prologue: prefetch pairs 0..2 ----
    #pragma unroll
    for (int pp = 0; pp < 3; pp++) { refill(pp, pp); CPC(); }

    ull ca[8], cb[8]; float cp[12];
    CPW(2);
    ldpair(0, ca, cb);
    refill(3, 0); CPC();
    partials(ca, cb, cp);

    #pragma unroll 3
    for (int p = 0; p < 27; p++) {
        ull na[8], nb[8]; float np[12];
        CPW(2);
        ldpair((p+1)%3, na, nb);
        if (p <= 23) refill(p+4, (p+1)%3);
        CPC();
        partials(na, nb, np);          // independent FMAs fill shuffle stalls

        reduce12(cp);
        update(cp, ca, cb, 1.f);       // pairs 0..26: both rows valid

        #pragma unroll
        for (int k = 0; k < 8; k++) { ca[k] = na[k]; cb[k] = nb[k]; }
        #pragma unroll
        for (int k = 0; k < 12; k++) cp[k] = np[k];
    }
    // tail: pair 27
    {
        reduce12(cp);
        float validB = (55 < cnt) ? 1.f : 0.f;
        update(cp, ca, cb, validB);
    }

    // ---- block combine (se/am are warp-uniform) ----
    if (lane == 0) {
        sm_se[warp][0]=se0; sm_se[warp][1]=se1; sm_se[warp][2]=se2; sm_se[warp][3]=se3;
        sm_am[warp][0]=am0; sm_am[warp][1]=am1; sm_am[warp][2]=am2; sm_am[warp][3]=am3;
    }
    // ---- stage zx into (now dead) ring smem: warp w owns ring[w*2048..] ----
    CPW(0);
    __syncthreads();     // all warps done with ring slots AND sm_se/sm_am written
    if (tid < H) {
        int h = tid;
        float bse = 0.f, bam = 0.f;
        #pragma unroll
        for (int w = 0; w < K3_WARPS; w++) { bse += sm_se[w][h]; bam += sm_am[w][h]; }
        g_pse[h*NB + blockIdx.x] = bse;
        g_pam[h*NB + blockIdx.x] = bam;
    }
    {
        float z0[16], z1[16], z2[16], z3[16];
        #pragma unroll
        for (int k = 0; k < 8; k++) {
            upk2(zx0[k], z0[2*k], z0[2*k+1]);
            upk2(zx1[k], z1[2*k], z1[2*k+1]);
            upk2(zx2[k], z2[2*k], z2[2*k+1]);
            upk2(zx3[k], z3[2*k], z3[2*k+1]);
        }
        float* wb = ring + warp*2048;
        #pragma unroll
        for (int j = 0; j < 4; j++) {
            *reinterpret_cast<float4*>(wb + 0*512 + j*128 + 4*lane) =
                make_float4(z0[4*j], z0[4*j+1], z0[4*j+2], z0[4*j+3]);
            *reinterpret_cast<float4*>(wb + 1*512 + j*128 + 4*lane) =
                make_float4(z1[4*j], z1[4*j+1], z1[4*j+2], z1[4*j+3]);
            *reinterpret_cast<float4*>(wb + 2*512 + j*128 + 4*lane) =
                make_float4(z2[4*j], z2[4*j+1], z2[4*j+2], z2[4*j+3]);
            *reinterpret_cast<float4*>(wb + 3*512 + j*128 + 4*lane) =
                make_float4(z3[4*j], z3[4*j+1], z3[4*j+2], z3[4*j+3]);
        }
    }
    __syncthreads();
    // ---- tree-reduce 8 warp copies -> g_pzx (dense float4, no conflicts) ----
    {
        float4 a = make_float4(0.f,0.f,0.f,0.f);
        float4 b = make_float4(0.f,0.f,0.f,0.f);
        #pragma unroll
        for (int w = 0; w < K3_WARPS; w++) {
            float4 va = *reinterpret_cast<const float4*>(ring + w*2048 + 4*tid);
            float4 vb = *reinterpret_cast<const float4*>(ring + w*2048 + 1024 + 4*tid);
            a.x += va.x; a.y += va.y; a.z += va.z; a.w += va.w;
            b.x += vb.x; b.y += vb.y; b.z += vb.z; b.w += vb.w;
        }
        float4* out4 = reinterpret_cast<float4*>(g_pzx + (size_t)blockIdx.x*(H*D));
        out4[tid]       = a;
        out4[256 + tid] = b;
    }
}

// ========= K_EPI: z -> o_pre -> y -> h1 -> out, fused with barriers ========
// grid 64 x 256
__global__ void __launch_bounds__(256, 1)
k_epi(const float* __restrict__ x,     const float* __restrict__ w_in,
      const float* __restrict__ b_in,  const float* __restrict__ w_out,
      const float* __restrict__ b_out, const float* __restrict__ w1,
      const float* __restrict__ b1,    const float* __restrict__ w2,
      const float* __restrict__ b2,    const float* __restrict__ g1,
      const float* __restrict__ be1,   const float* __restrict__ g2,
      const float* __restrict__ be2,   float* __restrict__ out) {
    __shared__ float part[8][32];
    __shared__ float sSE, sAM;
    int tid = threadIdx.x, lane = tid & 31, warp = tid >> 5;
    int r = blockIdx.x*8 + warp;   // row for GEMV phases

    // ---- phase A: z = g1*(sum_b ZX - AM)/SE + be1  (h = b>>4, 32 cols) ----
    {
        int h = blockIdx.x >> 4;
        int dbase = (blockIdx.x & 15) * 32;
        if (warp == 0) {
            float se = 0.f;
            #pragma unroll
            for (int b = lane; b < NB; b += 32) se += g_pse[h*NB + b];
            se = redux_add(se);
            if (lane == 0) sSE = se;
        } else if (warp == 1) {
            float am = 0.f;
            #pragma unroll
            for (int b = lane; b < NB; b += 32) am += g_pam[h*NB + b];
            am = redux_add(am);
            if (lane == 0) sAM = am;
        }
        float acc = 0.f;
        int b0 = warp * 19;
        int be = b0 + 19 < NB ? b0 + 19 : NB;
        #pragma unroll 5
        for (int b = b0; b < be; b++)
            acc += g_pzx[(size_t)b*(H*D) + h*D + dbase + lane];
        part[warp][lane] = acc;
        __syncthreads();
        if (warp == 0) {
            float s = part[0][lane];
            #pragma unroll
            for (int w = 1; w < 8; w++) s += part[w][lane];
            int d = dbase + lane;
            g_z[h*D + d] = g1[d] * (s - sAM) / sSE + be1[d];
        }
    }
    gbar(&g_bar2, 64);

    // ---- phase B: o_pre[r] = dot(Wv[r], z_head) + bv[r] ----
    {
        const float4* w4 = reinterpret_cast<const float4*>(w_in + (size_t)(2*D + r) * D);
        const float4* v4 = reinterpret_cast<const float4*>(g_z + (r >> 7) * D);
        float acc = dot512(w4, v4, lane);
        if (lane == 0) g_opre[r] = acc + b_in[2*D + r];
    }
    gbar(&g_bar2, 128);

    // ---- phase C: y[r] = x[r] + dot(w_out[r], o_pre) + b_out[r] ----
    {
        const float4* w4 = reinterpret_cast<const float4*>(w_out + (size_t)r * D);
        const float4* v4 = reinterpret_cast<const float4*>(g_opre);
        float acc = dot512(w4, v4, lane);
        if (lane == 0) g_y[r] = x[r] + acc + b_out[r];
    }
    gbar(&g_bar2, 192);

    // ---- phase D: h1[r] = relu(dot(w1[r], LN(y,g2,be2)) + b1[r]) ----
    {
        const float4* y4 = reinterpret_cast<const float4*>(g_y);
        float4 yl[4]; float s1 = 0.f, s2 = 0.f;
        #pragma unroll
        for (int j = 0; j < 4; j++) {
            yl[j] = y4[lane + 32*j];
            s1 += yl[j].x + yl[j].y + yl[j].z + yl[j].w;
            s2 = fmaf(yl[j].x, yl[j].x, s2); s2 = fmaf(yl[j].y, yl[j].y, s2);
            s2 = fmaf(yl[j].z, yl[j].z, s2); s2 = fmaf(yl[j].w, yl[j].w, s2);
        }
        s1 = redux_add(s1); s2 = redux_add(s2);
        float mean = s1 * (1.f/D);
        float rstd = rsq(s2 * (1.f/D) - mean*mean + 1e-5f);

        const float4* g24  = reinterpret_cast<const float4*>(g2);
        const float4* be24 = reinterpret_cast<const float4*>(be2);
        const float4* w4   = reinterpret_cast<const float4*>(w1 + (size_t)r * D);
        float acc = 0.f;
        #pragma unroll
        for (int j = 0; j < 4; j++) {
            float4 g = g24[lane + 32*j], b = be24[lane + 32*j], w = w4[lane + 32*j];
            float nx = (yl[j].x - mean)*rstd*g.x + b.x;
            float ny = (yl[j].y - mean)*rstd*g.y + b.y;
            float nz = (yl[j].z - mean)*rstd*g.z + b.z;
            float nw = (yl[j].w - mean)*rstd*g.w + b.w;
            acc = fmaf(w.x, nx, acc); acc = fmaf(w.y, ny, acc);
            acc = fmaf(w.z, nz, acc); acc = fmaf(w.w, nw, acc);
        }
        acc = redux_add(acc);
        if (lane == 0) g_h1[r] = fmaxf(acc + b1[r], 0.f);
    }
    gbar(&g_bar2, 256);

    // ---- phase E: out[r] = y[r] + dot(w2[r], h1) + b2[r] ----
    {
        const float4* w4 = reinterpret_cast<const float4*>(w2 + (size_t)r * D);
        const float4* v4 = reinterpret_cast<const float4*>(g_h1);
        float acc = dot512(w4, v4, lane);
        if (lane == 0) out[r] = g_y[r] + acc + b2[r];
    }
    gbar_final(&g_bar2, 320);
}

// ===========================================================================
extern "C" void kernel_launch(void* const* d_in, const int* in_sizes, int n_in,
                              void* d_out, int out_size) {
    const float* x     = (const float*)d_in[0];
    const float* w_in  = (const float*)d_in[1];
    const float* b_in  = (const float*)d_in[2];
    const float* w_out = (const float*)d_in[3];
    const float* b_out = (const float*)d_in[4];
    const float* w1    = (const float*)d_in[5];
    const float* b1    = (const float*)d_in[6];
    const float* w2    = (const float*)d_in[7];
    const float* b2    = (const float*)d_in[8];
    const float* g1    = (const float*)d_in[9];
    const float* be1   = (const float*)d_in[10];
    const float* g2    = (const float*)d_in[11];
    const float* be2   = (const float*)d_in[12];
    float* out = (float*)d_out;

    const int ringBytes = K3_WARPS * 3 * 1024 * (int)sizeof(float);   // 96 KB
    cudaFuncSetAttribute(k3_main, cudaFuncAttributeMaxDynamicSharedMemorySize, ringBytes);

    k12    <<<64, 256>>>(x, w_in, b_in, g1, be1);
    k3_main<<<NB, K3_THREADS, ringBytes>>>(x);
    k_epi  <<<64, 256>>>(x, w_in, b_in, w_out, b_out, w1, b1, w2, b2,
                         g1, be1, g2, be2, out);
}